// round 6
// baseline (speedup 1.0000x reference)
#include <cuda_runtime.h>
#include <cstdint>

#define BATCH   8
#define NN      512
#define DD      64
#define KNODES  256
#define TILE    32
#define NTILES  16      // NN / TILE
#define NPAIRS  136     // NTILES*(NTILES+1)/2
#define PAD_X   68
#define PAD_W   72

// Scratch (device globals: no allocation allowed)
__device__ float g_logits[BATCH * NN * NN];   // 8 MB
__device__ float g_h[BATCH * NN * DD];        // 1 MB
__device__ float g_scores[BATCH * NN];

// k1 dynamic smem layout (float offsets)
#define OFF_XI  0
#define OFF_XJ  (TILE * PAD_X)
#define OFF_WHI (2 * TILE * PAD_X)
#define OFF_WLO (OFF_WHI + DD * PAD_W)
#define OFF_PB  (OFF_WLO + DD * PAD_W)
#define OFF_AW  (OFF_PB + DD)
#define SMEM_FLOATS (OFF_AW + DD)
#define SMEM_BYTES  (SMEM_FLOATS * 4)

__device__ __forceinline__ float fast_tanh(float v) {
    float a = fabsf(v);
    float e = __expf(-2.0f * a);
    float r = __fdividef(1.0f - e, 1.0f + e);
    return copysignf(r, v);
}

__device__ __forceinline__ unsigned f2tf32(float f) {
    unsigned u;
    asm("cvt.rna.tf32.f32 %0, %1;" : "=r"(u) : "f"(f));
    return u;
}

__device__ __forceinline__ void mma_tf32(float* c,
                                         unsigned a0, unsigned a1, unsigned a2, unsigned a3,
                                         unsigned b0, unsigned b1) {
    asm("mma.sync.aligned.m16n8k8.row.col.f32.tf32.tf32.f32 "
        "{%0,%1,%2,%3}, {%4,%5,%6,%7}, {%8,%9}, {%0,%1,%2,%3};"
        : "+f"(c[0]), "+f"(c[1]), "+f"(c[2]), "+f"(c[3])
        : "r"(a0), "r"(a1), "r"(a2), "r"(a3), "r"(b0), "r"(b1));
}

// ---------------------------------------------------------------------------
// K1 (tensor-core, mma.sync): pairwise logits via 3xTF32 splits.
// Slim-warp layout: warp w owns j-half (w&1) and i-group (w>>2... w>>1);
// C[8][4] = 32 accum regs -> <=84 regs -> 3 CTAs/SM (6 warps/SMSP).
// Per ks: bh loaded once, used by hi and lo A (RAW dist-1 proven harmless).
// ---------------------------------------------------------------------------
__global__ __launch_bounds__(256, 3)
void k1_logits_tc(const float* __restrict__ x, const float* __restrict__ W,
                  const float* __restrict__ pb, const float* __restrict__ attw) {
    extern __shared__ float S[];

    int b = blockIdx.y;
    int pp = blockIdx.x;
    int it = 0;
    while (pp >= NTILES - it) { pp -= NTILES - it; it++; }
    int jt = it + pp;

    int t = threadIdx.x, w = t >> 5, lane = t & 31;
    int g = lane >> 2, cc = lane & 3;
    int h  = w & 1;         // j-half (0: j 0..15, 1: j 16..31)
    int ig = w >> 1;        // i-group (0..3), rows ig*8 .. ig*8+7

    // W splits: whi = tf32(W), wlo = tf32(W - whi). pad 72 -> conflict-free B LDS.
    for (int idx = t; idx < DD * DD; idx += 256) {
        int d = idx >> 6, o = idx & 63;
        float wv = W[idx];            // W[d][o] row-major
        unsigned hb = f2tf32(wv);
        float hf = __uint_as_float(hb);
        S[OFF_WHI + d * PAD_W + o] = hf;
        S[OFF_WLO + d * PAD_W + o] = __uint_as_float(f2tf32(wv - hf));
    }
    if (t < DD) { S[OFF_PB + t] = pb[t]; S[OFF_AW + t] = attw[t]; }
    const float* xb = x + (size_t)b * NN * DD;
    for (int idx = t; idx < TILE * 16; idx += 256) {
        int r = idx >> 4, c4 = idx & 15;
        float4 vi = ((const float4*)(xb + (it * TILE + r) * DD))[c4];
        *(float4*)&S[OFF_XI + r * PAD_X + c4 * 4] = vi;
        float4 vj = ((const float4*)(xb + (jt * TILE + r) * DD))[c4];
        *(float4*)&S[OFF_XJ + r * PAD_X + c4 * 4] = vj;
    }
    __syncthreads();

    float* L = g_logits + (size_t)b * NN * NN;
    int jb = h * 16;

    #pragma unroll 1
    for (int p = 0; p < 8; p++) {
        int iL = ig * 8 + p;               // this warp's i row (local)
        float C[8][4];                     // [o-tile][frag]  (one j-half)
        #pragma unroll
        for (int nt = 0; nt < 8; nt++)
            #pragma unroll
            for (int q = 0; q < 4; q++) C[nt][q] = 0.f;

        #pragma unroll 1
        for (int ks = 0; ks < 8; ks++) {
            int d0 = ks * 8;
            float xic0 = S[OFF_XI + iL * PAD_X + d0 + cc];
            float xic4 = S[OFF_XI + iL * PAD_X + d0 + cc + 4];
            float xj0 = S[OFF_XJ + (jb + g    ) * PAD_X + d0 + cc];
            float xj8 = S[OFF_XJ + (jb + g + 8) * PAD_X + d0 + cc];
            float yj0 = S[OFF_XJ + (jb + g    ) * PAD_X + d0 + cc + 4];
            float yj8 = S[OFF_XJ + (jb + g + 8) * PAD_X + d0 + cc + 4];
            float p0 = xic0 * xj0, p1 = xic0 * xj8;
            float p2 = xic4 * yj0, p3 = xic4 * yj8;
            unsigned ah0 = f2tf32(p0), ah1 = f2tf32(p1);
            unsigned ah2 = f2tf32(p2), ah3 = f2tf32(p3);
            unsigned al0 = f2tf32(p0 - __uint_as_float(ah0));
            unsigned al1 = f2tf32(p1 - __uint_as_float(ah1));
            unsigned al2 = f2tf32(p2 - __uint_as_float(ah2));
            unsigned al3 = f2tf32(p3 - __uint_as_float(ah3));

            // hi-passes: bh loaded once per nt, used twice (a_hi, a_lo)
            #pragma unroll
            for (int nt = 0; nt < 8; nt++) {
                int ob = nt * 8 + g;
                unsigned bh0 = __float_as_uint(S[OFF_WHI + (d0 + cc    ) * PAD_W + ob]);
                unsigned bh1 = __float_as_uint(S[OFF_WHI + (d0 + cc + 4) * PAD_W + ob]);
                mma_tf32(C[nt], ah0, ah1, ah2, ah3, bh0, bh1);
                mma_tf32(C[nt], al0, al1, al2, al3, bh0, bh1);
            }
            // lo-pass: a_hi * b_lo
            #pragma unroll
            for (int nt = 0; nt < 8; nt++) {
                int ob = nt * 8 + g;
                unsigned bl0 = __float_as_uint(S[OFF_WLO + (d0 + cc    ) * PAD_W + ob]);
                unsigned bl1 = __float_as_uint(S[OFF_WLO + (d0 + cc + 4) * PAD_W + ob]);
                mma_tf32(C[nt], ah0, ah1, ah2, ah3, bl0, bl1);
            }
        }
        // epilogue: tanh(C + pb) . attw, reduce over o (quad shuffle), store + mirror
        int gi = it * TILE + iL;
        float slo = 0.f, shi = 0.f;
        #pragma unroll
        for (int nt = 0; nt < 8; nt++) {
            int o0 = nt * 8 + 2 * cc, o1 = o0 + 1;
            float pb0 = S[OFF_PB + o0], pb1 = S[OFF_PB + o1];
            float w0  = S[OFF_AW + o0], w1  = S[OFF_AW + o1];
            slo = fmaf(fast_tanh(C[nt][0] + pb0), w0, slo);
            slo = fmaf(fast_tanh(C[nt][1] + pb1), w1, slo);
            shi = fmaf(fast_tanh(C[nt][2] + pb0), w0, shi);
            shi = fmaf(fast_tanh(C[nt][3] + pb1), w1, shi);
        }
        slo += __shfl_xor_sync(0xffffffffu, slo, 1);
        slo += __shfl_xor_sync(0xffffffffu, slo, 2);
        shi += __shfl_xor_sync(0xffffffffu, shi, 1);
        shi += __shfl_xor_sync(0xffffffffu, shi, 2);
        if (cc == 0) {
            int gj0 = jt * TILE + jb + g;
            int gj8 = gj0 + 8;
            L[gi * NN + gj0] = slo;
            L[gi * NN + gj8] = shi;
            if (it != jt) {
                L[gj0 * NN + gi] = slo;
                L[gj8 * NN + gi] = shi;
            }
        }
    }
}

// ---------------------------------------------------------------------------
// K2: per (b, 8-row block): softmax over j, agg = att @ X, h = agg@pwa + x@pwo
//     + biases, BN(eval), SELU, score = sigmoid(h @ pool_w + pool_b)
// ---------------------------------------------------------------------------
__global__ __launch_bounds__(256)
void k2_softagg(const float* __restrict__ x,
                const float* __restrict__ pwa_w, const float* __restrict__ pwa_b,
                const float* __restrict__ pwo_w, const float* __restrict__ pwo_b,
                const float* __restrict__ bn_gamma, const float* __restrict__ bn_beta,
                const float* __restrict__ pool_w, const float* __restrict__ pool_b) {
    __shared__ float prob_s[NN][8];        // 16 KB: [j][r]
    __shared__ float part_s[4][8][DD];     // 8 KB
    __shared__ float agg_s[8][DD];
    __shared__ float xrow_s[8][DD];
    __shared__ float h_s[8][DD];
    __shared__ float inv_s[8];

    int b = blockIdx.y;
    int ibase = blockIdx.x * 8;
    int t = threadIdx.x;
    const float* xb = x + (size_t)b * NN * DD;

    for (int idx = t; idx < 8 * DD; idx += 256) {
        int r = idx >> 6, d = idx & 63;
        xrow_s[r][d] = xb[(ibase + r) * DD + d];
    }

    {   // softmax (unnormalized) for 8 rows: warp r handles row ibase+r
        int r = t >> 5, lane = t & 31;
        const float* Lrow = g_logits + ((size_t)b * NN + ibase + r) * NN;
        float lv[16];
        float m = -1e30f;
        #pragma unroll
        for (int q = 0; q < 16; q++) { lv[q] = Lrow[lane + q * 32]; m = fmaxf(m, lv[q]); }
        #pragma unroll
        for (int off = 16; off; off >>= 1) m = fmaxf(m, __shfl_xor_sync(0xffffffffu, m, off));
        float sum = 0.f;
        #pragma unroll
        for (int q = 0; q < 16; q++) {
            float e = __expf(lv[q] - m);
            prob_s[lane + q * 32][r] = e;
            sum += e;
        }
        #pragma unroll
        for (int off = 16; off; off >>= 1) sum += __shfl_xor_sync(0xffffffffu, sum, off);
        if (lane == 0) inv_s[r] = 1.0f / sum;
    }
    __syncthreads();

    {   // agg partials: thread = (d4 in 16, g in 4, rp in 4) -> 4 d x 2 rows
        int d4 = t & 15, g = (t >> 4) & 3, rp = t >> 6;
        int r0 = rp * 2;
        float a0x=0,a0y=0,a0z=0,a0w=0, a1x=0,a1y=0,a1z=0,a1w=0;
        const float4* xb4 = (const float4*)xb;
        for (int jj = 0; jj < 128; jj++) {
            int j = g * 128 + jj;
            float4 xv = xb4[j * 16 + d4];
            float2 pr = *(const float2*)&prob_s[j][r0];
            a0x = fmaf(pr.x, xv.x, a0x); a0y = fmaf(pr.x, xv.y, a0y);
            a0z = fmaf(pr.x, xv.z, a0z); a0w = fmaf(pr.x, xv.w, a0w);
            a1x = fmaf(pr.y, xv.x, a1x); a1y = fmaf(pr.y, xv.y, a1y);
            a1z = fmaf(pr.y, xv.z, a1z); a1w = fmaf(pr.y, xv.w, a1w);
        }
        part_s[g][r0][d4*4+0] = a0x; part_s[g][r0][d4*4+1] = a0y;
        part_s[g][r0][d4*4+2] = a0z; part_s[g][r0][d4*4+3] = a0w;
        part_s[g][r0+1][d4*4+0] = a1x; part_s[g][r0+1][d4*4+1] = a1y;
        part_s[g][r0+1][d4*4+2] = a1z; part_s[g][r0+1][d4*4+3] = a1w;
    }
    __syncthreads();

    if (t < DD) {
        int d = t;
        #pragma unroll
        for (int r = 0; r < 8; r++) {
            float s = part_s[0][r][d] + part_s[1][r][d] + part_s[2][r][d] + part_s[3][r][d];
            agg_s[r][d] = s * inv_s[r];
        }
    }
    __syncthreads();

    {   // projections + BN + SELU: thread = (o in 64, rr in 4) -> 2 rows
        int o = t & 63, rr = t >> 6;
        int r0 = rr * 2, r1 = r0 + 1;
        float acc0 = pwa_b[o] + pwo_b[o];
        float acc1 = acc0;
        #pragma unroll 8
        for (int d = 0; d < DD; d++) {
            float wa = pwa_w[d * DD + o];
            float wo = pwo_w[d * DD + o];
            acc0 = fmaf(agg_s[r0][d], wa, acc0);
            acc0 = fmaf(xrow_s[r0][d], wo, acc0);
            acc1 = fmaf(agg_s[r1][d], wa, acc1);
            acc1 = fmaf(xrow_s[r1][d], wo, acc1);
        }
        const float BNF = 0.9999950000374997f;   // 1/sqrt(1+1e-5)
        float gm = bn_gamma[o] * BNF, bt = bn_beta[o];
        acc0 = acc0 * gm + bt;
        acc1 = acc1 * gm + bt;
        const float SC = 1.0507009873554805f, AL = 1.6732632423543772f;
        float v0 = acc0 > 0.f ? SC * acc0 : SC * AL * expm1f(acc0);
        float v1 = acc1 > 0.f ? SC * acc1 : SC * AL * expm1f(acc1);
        g_h[((size_t)b * NN + ibase + r0) * DD + o] = v0;
        g_h[((size_t)b * NN + ibase + r1) * DD + o] = v1;
        h_s[r0][o] = v0; h_s[r1][o] = v1;
    }
    __syncthreads();

    {   // pool scores
        int r = t >> 5, lane = t & 31;
        float z = h_s[r][lane] * pool_w[lane] + h_s[r][lane + 32] * pool_w[lane + 32];
        #pragma unroll
        for (int off = 16; off; off >>= 1) z += __shfl_xor_sync(0xffffffffu, z, off);
        if (lane == 0) {
            z += pool_b[0];
            g_scores[b * NN + ibase + r] = __fdividef(1.0f, 1.0f + __expf(-z));
        }
    }
}

// ---------------------------------------------------------------------------
// K3: per batch: full bitonic sort of 512 (score desc, idx asc) keys,
//     emit top-256 rows of h*score in rank order.
// ---------------------------------------------------------------------------
__global__ __launch_bounds__(512)
void k3_topk(float* __restrict__ out) {
    __shared__ unsigned long long keys[NN];
    __shared__ int   s_idx[KNODES];
    __shared__ float s_sc[KNODES];
    int b = blockIdx.x, t = threadIdx.x;
    float s = g_scores[b * NN + t];
    // scores in (0,1): positive-float bit pattern is order-preserving.
    keys[t] = ((unsigned long long)__float_as_uint(s) << 16) | (unsigned)(0xFFFF - t);
    __syncthreads();
    for (int k = 2; k <= NN; k <<= 1) {
        for (int j = k >> 1; j > 0; j >>= 1) {
            int ixj = t ^ j;
            if (ixj > t) {
                unsigned long long a = keys[t], c = keys[ixj];
                bool sw = ((t & k) == 0) ? (a < c) : (a > c);   // descending
                if (sw) { keys[t] = c; keys[ixj] = a; }
            }
            __syncthreads();
        }
    }
    if (t < KNODES) {
        unsigned long long kk = keys[t];
        s_idx[t] = 0xFFFF - (int)(kk & 0xFFFF);
        s_sc[t] = __uint_as_float((unsigned)(kk >> 16));
    }
    __syncthreads();
    const float* hb = g_h + (size_t)b * NN * DD;
    float* ob = out + (size_t)b * KNODES * DD;
    for (int e = t; e < KNODES * DD; e += 512) {
        int r = e >> 6, o = e & 63;
        ob[e] = hb[s_idx[r] * DD + o] * s_sc[r];
    }
}

extern "C" void kernel_launch(void* const* d_in, const int* in_sizes, int n_in,
                              void* d_out, int out_size) {
    const float* x     = (const float*)d_in[0];
    const float* apw   = (const float*)d_in[1];
    const float* apb   = (const float*)d_in[2];
    const float* attw  = (const float*)d_in[3];
    const float* pwa_w = (const float*)d_in[4];
    const float* pwa_b = (const float*)d_in[5];
    const float* pwo_w = (const float*)d_in[6];
    const float* pwo_b = (const float*)d_in[7];
    const float* bng   = (const float*)d_in[8];
    const float* bnb   = (const float*)d_in[9];
    const float* plw   = (const float*)d_in[10];
    const float* plb   = (const float*)d_in[11];
    float* out = (float*)d_out;

    cudaFuncSetAttribute(k1_logits_tc, cudaFuncAttributeMaxDynamicSharedMemorySize, SMEM_BYTES);
    k1_logits_tc<<<dim3(NPAIRS, BATCH), 256, SMEM_BYTES>>>(x, apw, apb, attw);
    k2_softagg<<<dim3(NN / 8, BATCH), 256>>>(x, pwa_w, pwa_b, pwo_w, pwo_b,
                                             bng, bnb, plw, plb);
    k3_topk<<<BATCH, 512>>>(out);
}

// round 7
// speedup vs baseline: 1.0694x; 1.0694x over previous
#include <cuda_runtime.h>
#include <cstdint>

#define BATCH   8
#define NN      512
#define DD      64
#define KNODES  256
#define TILE    32
#define NTILES  16      // NN / TILE
#define NPAIRS  136     // NTILES*(NTILES+1)/2

// Scratch (device globals: no allocation allowed)
__device__ float g_logits[BATCH * NN * NN];   // 8 MB
__device__ float g_h[BATCH * NN * DD];        // 1 MB
__device__ float g_scores[BATCH * NN];

// k1 dynamic smem layout (float offsets). Paired (float2) operand layouts:
//  WPH/WPL: [ks][o][cc] -> {W[8ks+cc][o], W[8ks+cc+4][o]}   8*64*4 float2
//  XIP/XJP: [ks][r][cc] -> {x[r][8ks+cc], x[r][8ks+cc+4]}   8*32*4 float2
#define OFF_WPH 0
#define OFF_WPL 4096
#define OFF_XIP 8192
#define OFF_XJP 10240
#define OFF_PB  12288
#define OFF_AW  12352
#define SMEM_FLOATS 12416
#define SMEM_BYTES  (SMEM_FLOATS * 4)

__device__ __forceinline__ float fast_tanh(float v) {
    float a = fabsf(v);
    float e = __expf(-2.0f * a);
    float r = __fdividef(1.0f - e, 1.0f + e);
    return copysignf(r, v);
}

__device__ __forceinline__ unsigned f2tf32(float f) {
    unsigned u;
    asm("cvt.rna.tf32.f32 %0, %1;" : "=r"(u) : "f"(f));
    return u;
}

__device__ __forceinline__ void mma_tf32(float* c,
                                         unsigned a0, unsigned a1, unsigned a2, unsigned a3,
                                         unsigned b0, unsigned b1) {
    asm("mma.sync.aligned.m16n8k8.row.col.f32.tf32.tf32.f32 "
        "{%0,%1,%2,%3}, {%4,%5,%6,%7}, {%8,%9}, {%0,%1,%2,%3};"
        : "+f"(c[0]), "+f"(c[1]), "+f"(c[2]), "+f"(c[3])
        : "r"(a0), "r"(a1), "r"(a2), "r"(a3), "r"(b0), "r"(b1));
}

// ---------------------------------------------------------------------------
// K1 (tensor-core, mma.sync): pairwise logits via 3xTF32 splits.
// Round-4 wide tile (C[2][8][4], 2 CTAs/SM) + float2-paired operands
// (every fragment = one coalesced LDS.64) + merged-bh pass.
// ---------------------------------------------------------------------------
__global__ __launch_bounds__(256, 2)
void k1_logits_tc(const float* __restrict__ x, const float* __restrict__ W,
                  const float* __restrict__ pb, const float* __restrict__ attw) {
    extern __shared__ float S[];

    int b = blockIdx.y;
    int pp = blockIdx.x;
    int it = 0;
    while (pp >= NTILES - it) { pp -= NTILES - it; it++; }
    int jt = it + pp;

    int t = threadIdx.x, w = t >> 5, lane = t & 31;
    int g = lane >> 2, cc = lane & 3;

    // Build paired W splits: one float2 per fragment (rows d0+cc, d0+cc+4)
    for (int idx = t; idx < 2048; idx += 256) {
        int ks = idx >> 8, rem = idx & 255;
        int o = rem >> 2, c2 = rem & 3;
        int d = 8 * ks + c2;
        float wv0 = W[d * DD + o];
        float wv1 = W[(d + 4) * DD + o];
        unsigned h0 = f2tf32(wv0), h1 = f2tf32(wv1);
        float hf0 = __uint_as_float(h0), hf1 = __uint_as_float(h1);
        *(float2*)&S[OFF_WPH + 2 * idx] = make_float2(hf0, hf1);
        *(float2*)&S[OFF_WPL + 2 * idx] =
            make_float2(__uint_as_float(f2tf32(wv0 - hf0)),
                        __uint_as_float(f2tf32(wv1 - hf1)));
    }
    if (t < DD) { S[OFF_PB + t] = pb[t]; S[OFF_AW + t] = attw[t]; }
    const float* xb = x + (size_t)b * NN * DD;
    for (int idx = t; idx < 1024; idx += 256) {
        int ks = idx >> 7, rem = idx & 127;
        int r = rem >> 2, c2 = rem & 3;
        int d = 8 * ks + c2;
        const float* xi = xb + (it * TILE + r) * DD;
        const float* xj = xb + (jt * TILE + r) * DD;
        *(float2*)&S[OFF_XIP + 2 * idx] = make_float2(xi[d], xi[d + 4]);
        *(float2*)&S[OFF_XJP + 2 * idx] = make_float2(xj[d], xj[d + 4]);
    }
    __syncthreads();

    float* L = g_logits + (size_t)b * NN * NN;

    #pragma unroll 1
    for (int p = 0; p < 4; p++) {
        int iL = 4 * w + p;                 // this warp's i row (local)
        float C[2][8][4];                   // [j-half][o-tile][frag]
        #pragma unroll
        for (int h = 0; h < 2; h++)
            #pragma unroll
            for (int nt = 0; nt < 8; nt++)
                #pragma unroll
                for (int q = 0; q < 4; q++) C[h][nt][q] = 0.f;

        #pragma unroll 1
        for (int ks = 0; ks < 8; ks++) {
            float2 ai = *(const float2*)&S[OFF_XIP + 2 * ((ks * TILE + iL) * 4 + cc)];
            unsigned ah[2][4], al[2][4];
            #pragma unroll
            for (int h = 0; h < 2; h++) {
                int jb = h * 16;
                float2 aj0 = *(const float2*)&S[OFF_XJP + 2 * ((ks * TILE + jb + g    ) * 4 + cc)];
                float2 aj8 = *(const float2*)&S[OFF_XJP + 2 * ((ks * TILE + jb + g + 8) * 4 + cc)];
                float p0 = ai.x * aj0.x, p1 = ai.x * aj8.x;
                float p2 = ai.y * aj0.y, p3 = ai.y * aj8.y;
                ah[h][0] = f2tf32(p0); al[h][0] = f2tf32(p0 - __uint_as_float(ah[h][0]));
                ah[h][1] = f2tf32(p1); al[h][1] = f2tf32(p1 - __uint_as_float(ah[h][1]));
                ah[h][2] = f2tf32(p2); al[h][2] = f2tf32(p2 - __uint_as_float(ah[h][2]));
                ah[h][3] = f2tf32(p3); al[h][3] = f2tf32(p3 - __uint_as_float(ah[h][3]));
            }
            // hi pass: one LDS.64 per nt feeds 4 MMAs (a_hi and a_lo x both halves)
            #pragma unroll
            for (int nt = 0; nt < 8; nt++) {
                int ob = nt * 8 + g;
                float2 bh = *(const float2*)&S[OFF_WPH + 2 * ((ks * DD + ob) * 4 + cc)];
                unsigned bh0 = __float_as_uint(bh.x), bh1 = __float_as_uint(bh.y);
                mma_tf32(C[0][nt], ah[0][0], ah[0][1], ah[0][2], ah[0][3], bh0, bh1);
                mma_tf32(C[1][nt], ah[1][0], ah[1][1], ah[1][2], ah[1][3], bh0, bh1);
                mma_tf32(C[0][nt], al[0][0], al[0][1], al[0][2], al[0][3], bh0, bh1);
                mma_tf32(C[1][nt], al[1][0], al[1][1], al[1][2], al[1][3], bh0, bh1);
            }
            // lo pass: a_hi * b_lo
            #pragma unroll
            for (int nt = 0; nt < 8; nt++) {
                int ob = nt * 8 + g;
                float2 bl = *(const float2*)&S[OFF_WPL + 2 * ((ks * DD + ob) * 4 + cc)];
                unsigned bl0 = __float_as_uint(bl.x), bl1 = __float_as_uint(bl.y);
                mma_tf32(C[0][nt], ah[0][0], ah[0][1], ah[0][2], ah[0][3], bl0, bl1);
                mma_tf32(C[1][nt], ah[1][0], ah[1][1], ah[1][2], ah[1][3], bl0, bl1);
            }
        }
        // epilogue: tanh(C + pb) . attw, reduce over o (quad shuffle), store + mirror
        int gi = it * TILE + iL;
        #pragma unroll
        for (int h = 0; h < 2; h++) {
            float slo = 0.f, shi = 0.f;
            #pragma unroll
            for (int nt = 0; nt < 8; nt++) {
                int o0 = nt * 8 + 2 * cc, o1 = o0 + 1;
                float pb0 = S[OFF_PB + o0], pb1 = S[OFF_PB + o1];
                float w0  = S[OFF_AW + o0], w1  = S[OFF_AW + o1];
                slo = fmaf(fast_tanh(C[h][nt][0] + pb0), w0, slo);
                slo = fmaf(fast_tanh(C[h][nt][1] + pb1), w1, slo);
                shi = fmaf(fast_tanh(C[h][nt][2] + pb0), w0, shi);
                shi = fmaf(fast_tanh(C[h][nt][3] + pb1), w1, shi);
            }
            slo += __shfl_xor_sync(0xffffffffu, slo, 1);
            slo += __shfl_xor_sync(0xffffffffu, slo, 2);
            shi += __shfl_xor_sync(0xffffffffu, shi, 1);
            shi += __shfl_xor_sync(0xffffffffu, shi, 2);
            if (cc == 0) {
                int gj0 = jt * TILE + h * 16 + g;
                int gj8 = gj0 + 8;
                L[gi * NN + gj0] = slo;
                L[gi * NN + gj8] = shi;
                if (it != jt) {
                    L[gj0 * NN + gi] = slo;
                    L[gj8 * NN + gi] = shi;
                }
            }
        }
    }
}

// ---------------------------------------------------------------------------
// K2: per (b, 8-row block): softmax over j, agg = att @ X, h = agg@pwa + x@pwo
//     + biases, BN(eval), SELU, score = sigmoid(h @ pool_w + pool_b)
// ---------------------------------------------------------------------------
__global__ __launch_bounds__(256)
void k2_softagg(const float* __restrict__ x,
                const float* __restrict__ pwa_w, const float* __restrict__ pwa_b,
                const float* __restrict__ pwo_w, const float* __restrict__ pwo_b,
                const float* __restrict__ bn_gamma, const float* __restrict__ bn_beta,
                const float* __restrict__ pool_w, const float* __restrict__ pool_b) {
    __shared__ float prob_s[NN][8];        // 16 KB: [j][r]
    __shared__ float part_s[4][8][DD];     // 8 KB
    __shared__ float agg_s[8][DD];
    __shared__ float xrow_s[8][DD];
    __shared__ float h_s[8][DD];
    __shared__ float inv_s[8];

    int b = blockIdx.y;
    int ibase = blockIdx.x * 8;
    int t = threadIdx.x;
    const float* xb = x + (size_t)b * NN * DD;

    for (int idx = t; idx < 8 * DD; idx += 256) {
        int r = idx >> 6, d = idx & 63;
        xrow_s[r][d] = xb[(ibase + r) * DD + d];
    }

    {   // softmax (unnormalized) for 8 rows: warp r handles row ibase+r
        int r = t >> 5, lane = t & 31;
        const float* Lrow = g_logits + ((size_t)b * NN + ibase + r) * NN;
        float lv[16];
        float m = -1e30f;
        #pragma unroll
        for (int q = 0; q < 16; q++) { lv[q] = Lrow[lane + q * 32]; m = fmaxf(m, lv[q]); }
        #pragma unroll
        for (int off = 16; off; off >>= 1) m = fmaxf(m, __shfl_xor_sync(0xffffffffu, m, off));
        float sum = 0.f;
        #pragma unroll
        for (int q = 0; q < 16; q++) {
            float e = __expf(lv[q] - m);
            prob_s[lane + q * 32][r] = e;
            sum += e;
        }
        #pragma unroll
        for (int off = 16; off; off >>= 1) sum += __shfl_xor_sync(0xffffffffu, sum, off);
        if (lane == 0) inv_s[r] = 1.0f / sum;
    }
    __syncthreads();

    {   // agg partials: thread = (d4 in 16, g in 4, rp in 4) -> 4 d x 2 rows
        int d4 = t & 15, g = (t >> 4) & 3, rp = t >> 6;
        int r0 = rp * 2;
        float a0x=0,a0y=0,a0z=0,a0w=0, a1x=0,a1y=0,a1z=0,a1w=0;
        const float4* xb4 = (const float4*)xb;
        for (int jj = 0; jj < 128; jj++) {
            int j = g * 128 + jj;
            float4 xv = xb4[j * 16 + d4];
            float2 pr = *(const float2*)&prob_s[j][r0];
            a0x = fmaf(pr.x, xv.x, a0x); a0y = fmaf(pr.x, xv.y, a0y);
            a0z = fmaf(pr.x, xv.z, a0z); a0w = fmaf(pr.x, xv.w, a0w);
            a1x = fmaf(pr.y, xv.x, a1x); a1y = fmaf(pr.y, xv.y, a1y);
            a1z = fmaf(pr.y, xv.z, a1z); a1w = fmaf(pr.y, xv.w, a1w);
        }
        part_s[g][r0][d4*4+0] = a0x; part_s[g][r0][d4*4+1] = a0y;
        part_s[g][r0][d4*4+2] = a0z; part_s[g][r0][d4*4+3] = a0w;
        part_s[g][r0+1][d4*4+0] = a1x; part_s[g][r0+1][d4*4+1] = a1y;
        part_s[g][r0+1][d4*4+2] = a1z; part_s[g][r0+1][d4*4+3] = a1w;
    }
    __syncthreads();

    if (t < DD) {
        int d = t;
        #pragma unroll
        for (int r = 0; r < 8; r++) {
            float s = part_s[0][r][d] + part_s[1][r][d] + part_s[2][r][d] + part_s[3][r][d];
            agg_s[r][d] = s * inv_s[r];
        }
    }
    __syncthreads();

    {   // projections + BN + SELU: thread = (o in 64, rr in 4) -> 2 rows
        int o = t & 63, rr = t >> 6;
        int r0 = rr * 2, r1 = r0 + 1;
        float acc0 = pwa_b[o] + pwo_b[o];
        float acc1 = acc0;
        #pragma unroll 8
        for (int d = 0; d < DD; d++) {
            float wa = pwa_w[d * DD + o];
            float wo = pwo_w[d * DD + o];
            acc0 = fmaf(agg_s[r0][d], wa, acc0);
            acc0 = fmaf(xrow_s[r0][d], wo, acc0);
            acc1 = fmaf(agg_s[r1][d], wa, acc1);
            acc1 = fmaf(xrow_s[r1][d], wo, acc1);
        }
        const float BNF = 0.9999950000374997f;   // 1/sqrt(1+1e-5)
        float gm = bn_gamma[o] * BNF, bt = bn_beta[o];
        acc0 = acc0 * gm + bt;
        acc1 = acc1 * gm + bt;
        const float SC = 1.0507009873554805f, AL = 1.6732632423543772f;
        float v0 = acc0 > 0.f ? SC * acc0 : SC * AL * expm1f(acc0);
        float v1 = acc1 > 0.f ? SC * acc1 : SC * AL * expm1f(acc1);
        g_h[((size_t)b * NN + ibase + r0) * DD + o] = v0;
        g_h[((size_t)b * NN + ibase + r1) * DD + o] = v1;
        h_s[r0][o] = v0; h_s[r1][o] = v1;
    }
    __syncthreads();

    {   // pool scores
        int r = t >> 5, lane = t & 31;
        float z = h_s[r][lane] * pool_w[lane] + h_s[r][lane + 32] * pool_w[lane + 32];
        #pragma unroll
        for (int off = 16; off; off >>= 1) z += __shfl_xor_sync(0xffffffffu, z, off);
        if (lane == 0) {
            z += pool_b[0];
            g_scores[b * NN + ibase + r] = __fdividef(1.0f, 1.0f + __expf(-z));
        }
    }
}

// ---------------------------------------------------------------------------
// K3: per batch: full bitonic sort of 512 (score desc, idx asc) keys,
//     emit top-256 rows of h*score in rank order.
// ---------------------------------------------------------------------------
__global__ __launch_bounds__(512)
void k3_topk(float* __restrict__ out) {
    __shared__ unsigned long long keys[NN];
    __shared__ int   s_idx[KNODES];
    __shared__ float s_sc[KNODES];
    int b = blockIdx.x, t = threadIdx.x;
    float s = g_scores[b * NN + t];
    // scores in (0,1): positive-float bit pattern is order-preserving.
    keys[t] = ((unsigned long long)__float_as_uint(s) << 16) | (unsigned)(0xFFFF - t);
    __syncthreads();
    for (int k = 2; k <= NN; k <<= 1) {
        for (int j = k >> 1; j > 0; j >>= 1) {
            int ixj = t ^ j;
            if (ixj > t) {
                unsigned long long a = keys[t], c = keys[ixj];
                bool sw = ((t & k) == 0) ? (a < c) : (a > c);   // descending
                if (sw) { keys[t] = c; keys[ixj] = a; }
            }
            __syncthreads();
        }
    }
    if (t < KNODES) {
        unsigned long long kk = keys[t];
        s_idx[t] = 0xFFFF - (int)(kk & 0xFFFF);
        s_sc[t] = __uint_as_float((unsigned)(kk >> 16));
    }
    __syncthreads();
    const float* hb = g_h + (size_t)b * NN * DD;
    float* ob = out + (size_t)b * KNODES * DD;
    for (int e = t; e < KNODES * DD; e += 512) {
        int r = e >> 6, o = e & 63;
        ob[e] = hb[s_idx[r] * DD + o] * s_sc[r];
    }
}

extern "C" void kernel_launch(void* const* d_in, const int* in_sizes, int n_in,
                              void* d_out, int out_size) {
    const float* x     = (const float*)d_in[0];
    const float* apw   = (const float*)d_in[1];
    const float* apb   = (const float*)d_in[2];
    const float* attw  = (const float*)d_in[3];
    const float* pwa_w = (const float*)d_in[4];
    const float* pwa_b = (const float*)d_in[5];
    const float* pwo_w = (const float*)d_in[6];
    const float* pwo_b = (const float*)d_in[7];
    const float* bng   = (const float*)d_in[8];
    const float* bnb   = (const float*)d_in[9];
    const float* plw   = (const float*)d_in[10];
    const float* plb   = (const float*)d_in[11];
    float* out = (float*)d_out;

    cudaFuncSetAttribute(k1_logits_tc, cudaFuncAttributeMaxDynamicSharedMemorySize, SMEM_BYTES);
    k1_logits_tc<<<dim3(NPAIRS, BATCH), 256, SMEM_BYTES>>>(x, apw, apb, attw);
    k2_softagg<<<dim3(NN / 8, BATCH), 256>>>(x, pwa_w, pwa_b, pwo_w, pwo_b,
                                             bng, bnb, plw, plb);
    k3_topk<<<BATCH, 512>>>(out);
}

// round 8
// speedup vs baseline: 1.5135x; 1.4153x over previous
#include <cuda_runtime.h>
#include <cuda_fp16.h>
#include <cstdint>

#define BATCH   8
#define NN      512
#define DD      64
#define KNODES  256
#define TILE    32
#define NTILES  16      // NN / TILE
#define NPAIRS  136     // NTILES*(NTILES+1)/2

// Scratch (device globals: no allocation allowed)
__device__ float g_logits[BATCH * NN * NN];   // 8 MB
__device__ float g_h[BATCH * NN * DD];        // 1 MB
__device__ float g_scores[BATCH * NN];

// k1 smem layout (float offsets)
//  WPH/WPL: uint2[4][64][4]: {half2(ws[16k+2c],ws[+1]), half2(ws[+8],ws[+9])}[o]
//           (ws = 16*W, fp16 hi/lo splits)
//  XIP/XJP: float4[4][32][4]: {x[r][16k+2c], [+1], [+8], [+9]}
#define OFF_WPH 0
#define OFF_WPL 2048
#define OFF_XIP 4096
#define OFF_XJP 6144
#define OFF_PB  8192
#define OFF_AW  8256
#define SMEM_FLOATS 8320
#define SMEM_BYTES  (SMEM_FLOATS * 4)

__device__ __forceinline__ float fast_tanh(float v) {
    float a = fabsf(v);
    float e = __expf(-2.0f * a);
    float r = __fdividef(1.0f - e, 1.0f + e);
    return copysignf(r, v);
}

__device__ __forceinline__ unsigned h2u(__half2 h) {
    return *reinterpret_cast<unsigned*>(&h);
}

__device__ __forceinline__ void mma_f16(float* c,
                                        unsigned a0, unsigned a1, unsigned a2, unsigned a3,
                                        unsigned b0, unsigned b1) {
    asm("mma.sync.aligned.m16n8k16.row.col.f32.f16.f16.f32 "
        "{%0,%1,%2,%3}, {%4,%5,%6,%7}, {%8,%9}, {%0,%1,%2,%3};"
        : "+f"(c[0]), "+f"(c[1]), "+f"(c[2]), "+f"(c[3])
        : "r"(a0), "r"(a1), "r"(a2), "r"(a3), "r"(b0), "r"(b1));
}

// ---------------------------------------------------------------------------
// K1 (tensor-core, fp16 m16n8k16, 3-split): pairwise logits.
// fp16 roundoff == tf32 roundoff (2^-11); k16 halves HMMA instruction count.
// W pre-scaled by 16 so wl splits stay fp16-normal; epilogue multiplies 1/16.
// A-role = j (16 rows), B-role = o (8 cols); i fixed per warp-iteration.
// ---------------------------------------------------------------------------
__global__ __launch_bounds__(256, 2)
void k1_logits_tc(const float* __restrict__ x, const float* __restrict__ W,
                  const float* __restrict__ pb, const float* __restrict__ attw) {
    extern __shared__ float S[];
    uint2*  WH  = (uint2*)&S[OFF_WPH];
    uint2*  WL  = (uint2*)&S[OFF_WPL];
    float4* XI4 = (float4*)&S[OFF_XIP];
    float4* XJ4 = (float4*)&S[OFF_XJP];

    int b = blockIdx.y;
    int pp = blockIdx.x;
    int it = 0;
    while (pp >= NTILES - it) { pp -= NTILES - it; it++; }
    int jt = it + pp;

    int t = threadIdx.x, w = t >> 5, lane = t & 31;
    int g = lane >> 2, cc = lane & 3;

    // Build W splits (scaled by 16): one uint2 per (ks16, o, cc)
    for (int idx = t; idx < 1024; idx += 256) {
        int o = idx & 63, c2 = (idx >> 6) & 3, ks = idx >> 8;
        int d0 = 16 * ks + 2 * c2;
        float w0 = 16.0f * W[(d0    ) * DD + o];
        float w1 = 16.0f * W[(d0 + 1) * DD + o];
        float w8 = 16.0f * W[(d0 + 8) * DD + o];
        float w9 = 16.0f * W[(d0 + 9) * DD + o];
        __half2 h01 = __floats2half2_rn(w0, w1);
        __half2 h89 = __floats2half2_rn(w8, w9);
        float2 f01 = __half22float2(h01);
        float2 f89 = __half22float2(h89);
        __half2 l01 = __floats2half2_rn(w0 - f01.x, w1 - f01.y);
        __half2 l89 = __floats2half2_rn(w8 - f89.x, w9 - f89.y);
        WH[(ks * 64 + o) * 4 + c2] = make_uint2(h2u(h01), h2u(h89));
        WL[(ks * 64 + o) * 4 + c2] = make_uint2(h2u(l01), h2u(l89));
    }
    if (t < DD) { S[OFF_PB + t] = pb[t]; S[OFF_AW + t] = attw[t]; }
    const float* xb = x + (size_t)b * NN * DD;
    for (int idx = t; idx < 512; idx += 256) {
        int ks = idx >> 7, r = (idx >> 2) & 31, c2 = idx & 3;
        int d0 = 16 * ks + 2 * c2;
        const float* xi = xb + (it * TILE + r) * DD;
        const float* xj = xb + (jt * TILE + r) * DD;
        XI4[idx] = make_float4(xi[d0], xi[d0 + 1], xi[d0 + 8], xi[d0 + 9]);
        XJ4[idx] = make_float4(xj[d0], xj[d0 + 1], xj[d0 + 8], xj[d0 + 9]);
    }
    __syncthreads();

    float* L = g_logits + (size_t)b * NN * NN;

    #pragma unroll 1
    for (int p = 0; p < 4; p++) {
        int iL = 4 * w + p;                 // this warp's i row (local)
        float C[2][8][4];                   // [j-half][o-tile][frag]
        #pragma unroll
        for (int h = 0; h < 2; h++)
            #pragma unroll
            for (int nt = 0; nt < 8; nt++)
                #pragma unroll
                for (int q = 0; q < 4; q++) C[h][nt][q] = 0.f;

        #pragma unroll 1
        for (int ks = 0; ks < 4; ks++) {
            float4 ai = XI4[(ks * TILE + iL) * 4 + cc];
            unsigned ah[2][4], al[2][4];
            #pragma unroll
            for (int h = 0; h < 2; h++) {
                int jb = h * 16;
                float4 ajg = XJ4[(ks * TILE + jb + g    ) * 4 + cc];
                float4 aj8 = XJ4[(ks * TILE + jb + g + 8) * 4 + cc];
                // products: rows (g, g+8), k = {2cc, 2cc+1, 2cc+8, 2cc+9}
                float pg0 = ai.x * ajg.x, pg1 = ai.y * ajg.y;
                float pg8 = ai.z * ajg.z, pg9 = ai.w * ajg.w;
                float q0  = ai.x * aj8.x, q1  = ai.y * aj8.y;
                float q8  = ai.z * aj8.z, q9  = ai.w * aj8.w;
                __half2 h0 = __floats2half2_rn(pg0, pg1);   // a0: row g, k lo
                __half2 h1 = __floats2half2_rn(q0, q1);     // a1: row g+8, k lo
                __half2 h2 = __floats2half2_rn(pg8, pg9);   // a2: row g, k hi
                __half2 h3 = __floats2half2_rn(q8, q9);     // a3: row g+8, k hi
                float2 f0 = __half22float2(h0), f1 = __half22float2(h1);
                float2 f2 = __half22float2(h2), f3 = __half22float2(h3);
                ah[h][0] = h2u(h0); ah[h][1] = h2u(h1);
                ah[h][2] = h2u(h2); ah[h][3] = h2u(h3);
                al[h][0] = h2u(__floats2half2_rn(pg0 - f0.x, pg1 - f0.y));
                al[h][1] = h2u(__floats2half2_rn(q0  - f1.x, q1  - f1.y));
                al[h][2] = h2u(__floats2half2_rn(pg8 - f2.x, pg9 - f2.y));
                al[h][3] = h2u(__floats2half2_rn(q8  - f3.x, q9  - f3.y));
            }
            // hi-b pass: one LDS.64 per nt feeds 4 MMAs (a_hi, a_lo x 2 halves)
            #pragma unroll
            for (int nt = 0; nt < 8; nt++) {
                uint2 bh = WH[(ks * DD + nt * 8 + g) * 4 + cc];
                mma_f16(C[0][nt], ah[0][0], ah[0][1], ah[0][2], ah[0][3], bh.x, bh.y);
                mma_f16(C[1][nt], ah[1][0], ah[1][1], ah[1][2], ah[1][3], bh.x, bh.y);
                mma_f16(C[0][nt], al[0][0], al[0][1], al[0][2], al[0][3], bh.x, bh.y);
                mma_f16(C[1][nt], al[1][0], al[1][1], al[1][2], al[1][3], bh.x, bh.y);
            }
            // lo-b pass: a_hi * b_lo
            #pragma unroll
            for (int nt = 0; nt < 8; nt++) {
                uint2 bl = WL[(ks * DD + nt * 8 + g) * 4 + cc];
                mma_f16(C[0][nt], ah[0][0], ah[0][1], ah[0][2], ah[0][3], bl.x, bl.y);
                mma_f16(C[1][nt], ah[1][0], ah[1][1], ah[1][2], ah[1][3], bl.x, bl.y);
            }
        }
        // epilogue: tanh(C/16 + pb) . attw, reduce over o (quad shuffle), store+mirror
        int gi = it * TILE + iL;
        #pragma unroll
        for (int h = 0; h < 2; h++) {
            float slo = 0.f, shi = 0.f;
            #pragma unroll
            for (int nt = 0; nt < 8; nt++) {
                int o0 = nt * 8 + 2 * cc, o1 = o0 + 1;
                float pb0 = S[OFF_PB + o0], pb1 = S[OFF_PB + o1];
                float w0  = S[OFF_AW + o0], w1  = S[OFF_AW + o1];
                slo = fmaf(fast_tanh(fmaf(C[h][nt][0], 0.0625f, pb0)), w0, slo);
                slo = fmaf(fast_tanh(fmaf(C[h][nt][1], 0.0625f, pb1)), w1, slo);
                shi = fmaf(fast_tanh(fmaf(C[h][nt][2], 0.0625f, pb0)), w0, shi);
                shi = fmaf(fast_tanh(fmaf(C[h][nt][3], 0.0625f, pb1)), w1, shi);
            }
            slo += __shfl_xor_sync(0xffffffffu, slo, 1);
            slo += __shfl_xor_sync(0xffffffffu, slo, 2);
            shi += __shfl_xor_sync(0xffffffffu, shi, 1);
            shi += __shfl_xor_sync(0xffffffffu, shi, 2);
            if (cc == 0) {
                int gj0 = jt * TILE + h * 16 + g;
                int gj8 = gj0 + 8;
                L[gi * NN + gj0] = slo;
                L[gi * NN + gj8] = shi;
                if (it != jt) {
                    L[gj0 * NN + gi] = slo;
                    L[gj8 * NN + gi] = shi;
                }
            }
        }
    }
}

// ---------------------------------------------------------------------------
// K2: per (b, 8-row block): softmax over j, agg = att @ X, h = agg@pwa + x@pwo
//     + biases, BN(eval), SELU, score = sigmoid(h @ pool_w + pool_b)
// ---------------------------------------------------------------------------
__global__ __launch_bounds__(256)
void k2_softagg(const float* __restrict__ x,
                const float* __restrict__ pwa_w, const float* __restrict__ pwa_b,
                const float* __restrict__ pwo_w, const float* __restrict__ pwo_b,
                const float* __restrict__ bn_gamma, const float* __restrict__ bn_beta,
                const float* __restrict__ pool_w, const float* __restrict__ pool_b) {
    __shared__ float prob_s[NN][8];        // 16 KB: [j][r]
    __shared__ float part_s[4][8][DD];     // 8 KB
    __shared__ float agg_s[8][DD];
    __shared__ float xrow_s[8][DD];
    __shared__ float h_s[8][DD];
    __shared__ float inv_s[8];

    int b = blockIdx.y;
    int ibase = blockIdx.x * 8;
    int t = threadIdx.x;
    const float* xb = x + (size_t)b * NN * DD;

    for (int idx = t; idx < 8 * DD; idx += 256) {
        int r = idx >> 6, d = idx & 63;
        xrow_s[r][d] = xb[(ibase + r) * DD + d];
    }

    {   // softmax (unnormalized) for 8 rows: warp r handles row ibase+r
        int r = t >> 5, lane = t & 31;
        const float* Lrow = g_logits + ((size_t)b * NN + ibase + r) * NN;
        float lv[16];
        float m = -1e30f;
        #pragma unroll
        for (int q = 0; q < 16; q++) { lv[q] = Lrow[lane + q * 32]; m = fmaxf(m, lv[q]); }
        #pragma unroll
        for (int off = 16; off; off >>= 1) m = fmaxf(m, __shfl_xor_sync(0xffffffffu, m, off));
        float sum = 0.f;
        #pragma unroll
        for (int q = 0; q < 16; q++) {
            float e = __expf(lv[q] - m);
            prob_s[lane + q * 32][r] = e;
            sum += e;
        }
        #pragma unroll
        for (int off = 16; off; off >>= 1) sum += __shfl_xor_sync(0xffffffffu, sum, off);
        if (lane == 0) inv_s[r] = 1.0f / sum;
    }
    __syncthreads();

    {   // agg partials: thread = (d4 in 16, g in 4, rp in 4) -> 4 d x 2 rows
        int d4 = t & 15, g = (t >> 4) & 3, rp = t >> 6;
        int r0 = rp * 2;
        float a0x=0,a0y=0,a0z=0,a0w=0, a1x=0,a1y=0,a1z=0,a1w=0;
        const float4* xb4 = (const float4*)xb;
        for (int jj = 0; jj < 128; jj++) {
            int j = g * 128 + jj;
            float4 xv = xb4[j * 16 + d4];
            float2 pr = *(const float2*)&prob_s[j][r0];
            a0x = fmaf(pr.x, xv.x, a0x); a0y = fmaf(pr.x, xv.y, a0y);
            a0z = fmaf(pr.x, xv.z, a0z); a0w = fmaf(pr.x, xv.w, a0w);
            a1x = fmaf(pr.y, xv.x, a1x); a1y = fmaf(pr.y, xv.y, a1y);
            a1z = fmaf(pr.y, xv.z, a1z); a1w = fmaf(pr.y, xv.w, a1w);
        }
        part_s[g][r0][d4*4+0] = a0x; part_s[g][r0][d4*4+1] = a0y;
        part_s[g][r0][d4*4+2] = a0z; part_s[g][r0][d4*4+3] = a0w;
        part_s[g][r0+1][d4*4+0] = a1x; part_s[g][r0+1][d4*4+1] = a1y;
        part_s[g][r0+1][d4*4+2] = a1z; part_s[g][r0+1][d4*4+3] = a1w;
    }
    __syncthreads();

    if (t < DD) {
        int d = t;
        #pragma unroll
        for (int r = 0; r < 8; r++) {
            float s = part_s[0][r][d] + part_s[1][r][d] + part_s[2][r][d] + part_s[3][r][d];
            agg_s[r][d] = s * inv_s[r];
        }
    }
    __syncthreads();

    {   // projections + BN + SELU: thread = (o in 64, rr in 4) -> 2 rows
        int o = t & 63, rr = t >> 6;
        int r0 = rr * 2, r1 = r0 + 1;
        float acc0 = pwa_b[o] + pwo_b[o];
        float acc1 = acc0;
        #pragma unroll 8
        for (int d = 0; d < DD; d++) {
            float wa = pwa_w[d * DD + o];
            float wo = pwo_w[d * DD + o];
            acc0 = fmaf(agg_s[r0][d], wa, acc0);
            acc0 = fmaf(xrow_s[r0][d], wo, acc0);
            acc1 = fmaf(agg_s[r1][d], wa, acc1);
            acc1 = fmaf(xrow_s[r1][d], wo, acc1);
        }
        const float BNF = 0.9999950000374997f;   // 1/sqrt(1+1e-5)
        float gm = bn_gamma[o] * BNF, bt = bn_beta[o];
        acc0 = acc0 * gm + bt;
        acc1 = acc1 * gm + bt;
        const float SC = 1.0507009873554805f, AL = 1.6732632423543772f;
        float v0 = acc0 > 0.f ? SC * acc0 : SC * AL * expm1f(acc0);
        float v1 = acc1 > 0.f ? SC * acc1 : SC * AL * expm1f(acc1);
        g_h[((size_t)b * NN + ibase + r0) * DD + o] = v0;
        g_h[((size_t)b * NN + ibase + r1) * DD + o] = v1;
        h_s[r0][o] = v0; h_s[r1][o] = v1;
    }
    __syncthreads();

    {   // pool scores
        int r = t >> 5, lane = t & 31;
        float z = h_s[r][lane] * pool_w[lane] + h_s[r][lane + 32] * pool_w[lane + 32];
        #pragma unroll
        for (int off = 16; off; off >>= 1) z += __shfl_xor_sync(0xffffffffu, z, off);
        if (lane == 0) {
            z += pool_b[0];
            g_scores[b * NN + ibase + r] = __fdividef(1.0f, 1.0f + __expf(-z));
        }
    }
}

// ---------------------------------------------------------------------------
// K3: per batch: full bitonic sort of 512 (score desc, idx asc) keys,
//     emit top-256 rows of h*score in rank order.
// ---------------------------------------------------------------------------
__global__ __launch_bounds__(512)
void k3_topk(float* __restrict__ out) {
    __shared__ unsigned long long keys[NN];
    __shared__ int   s_idx[KNODES];
    __shared__ float s_sc[KNODES];
    int b = blockIdx.x, t = threadIdx.x;
    float s = g_scores[b * NN + t];
    // scores in (0,1): positive-float bit pattern is order-preserving.
    keys[t] = ((unsigned long long)__float_as_uint(s) << 16) | (unsigned)(0xFFFF - t);
    __syncthreads();
    for (int k = 2; k <= NN; k <<= 1) {
        for (int j = k >> 1; j > 0; j >>= 1) {
            int ixj = t ^ j;
            if (ixj > t) {
                unsigned long long a = keys[t], c = keys[ixj];
                bool sw = ((t & k) == 0) ? (a < c) : (a > c);   // descending
                if (sw) { keys[t] = c; keys[ixj] = a; }
            }
            __syncthreads();
        }
    }
    if (t < KNODES) {
        unsigned long long kk = keys[t];
        s_idx[t] = 0xFFFF - (int)(kk & 0xFFFF);
        s_sc[t] = __uint_as_float((unsigned)(kk >> 16));
    }
    __syncthreads();
    const float* hb = g_h + (size_t)b * NN * DD;
    float* ob = out + (size_t)b * KNODES * DD;
    for (int e = t; e < KNODES * DD; e += 512) {
        int r = e >> 6, o = e & 63;
        ob[e] = hb[s_idx[r] * DD + o] * s_sc[r];
    }
}

extern "C" void kernel_launch(void* const* d_in, const int* in_sizes, int n_in,
                              void* d_out, int out_size) {
    const float* x     = (const float*)d_in[0];
    const float* apw   = (const float*)d_in[1];
    const float* apb   = (const float*)d_in[2];
    const float* attw  = (const float*)d_in[3];
    const float* pwa_w = (const float*)d_in[4];
    const float* pwa_b = (const float*)d_in[5];
    const float* pwo_w = (const float*)d_in[6];
    const float* pwo_b = (const float*)d_in[7];
    const float* bng   = (const float*)d_in[8];
    const float* bnb   = (const float*)d_in[9];
    const float* plw   = (const float*)d_in[10];
    const float* plb   = (const float*)d_in[11];
    float* out = (float*)d_out;

    cudaFuncSetAttribute(k1_logits_tc, cudaFuncAttributeMaxDynamicSharedMemorySize, SMEM_BYTES);
    k1_logits_tc<<<dim3(NPAIRS, BATCH), 256, SMEM_BYTES>>>(x, apw, apb, attw);
    k2_softagg<<<dim3(NN / 8, BATCH), 256>>>(x, pwa_w, pwa_b, pwo_w, pwo_b,
                                             bng, bnb, plw, plb);
    k3_topk<<<BATCH, 512>>>(out);
}

// round 9
// speedup vs baseline: 1.5238x; 1.0068x over previous
#include <cuda_runtime.h>
#include <cuda_fp16.h>
#include <cstdint>

#define BATCH   8
#define NN      512
#define DD      64
#define KNODES  256
#define TILE    32
#define NTILES  16      // NN / TILE
#define NPAIRS  136     // NTILES*(NTILES+1)/2
#define NITEMS  (BATCH * NPAIRS)   // 1088
#define K1GRID  296                // 2 CTAs/SM * 148 SMs

// Scratch (device globals: no allocation allowed)
__device__ float g_logits[BATCH * NN * NN];   // 8 MB
__device__ float g_h[BATCH * NN * DD];        // 1 MB
__device__ float g_scores[BATCH * NN];

// k1 smem layout (float offsets)
//  WP:  uint4[4][64][4]: .xy = {h2(ws[16k+2c],ws[+1]), h2(ws[+8],ws[+9])} hi
//                        .zw = same, lo split   (ws = 16*W)
//  XIP/XJP: float4[4][32][4]: {x[r][16k+2c], [+1], [+8], [+9]}
#define OFF_WP  0
#define OFF_XIP 4096
#define OFF_XJP 6144
#define OFF_PB  8192
#define OFF_AW  8256
#define SMEM_FLOATS 8320
#define SMEM_BYTES  (SMEM_FLOATS * 4)

__device__ __forceinline__ float fast_tanh(float v) {
    // 1 - 2/(e^{2v}+1): correct saturation both directions, no abs/copysign
    float e = __expf(2.0f * v);
    return 1.0f - __fdividef(2.0f, e + 1.0f);
}

__device__ __forceinline__ unsigned h2u(__half2 h) {
    return *reinterpret_cast<unsigned*>(&h);
}

__device__ __forceinline__ void mma_f16(float* c,
                                        unsigned a0, unsigned a1, unsigned a2, unsigned a3,
                                        unsigned b0, unsigned b1) {
    asm("mma.sync.aligned.m16n8k16.row.col.f32.f16.f16.f32 "
        "{%0,%1,%2,%3}, {%4,%5,%6,%7}, {%8,%9}, {%0,%1,%2,%3};"
        : "+f"(c[0]), "+f"(c[1]), "+f"(c[2]), "+f"(c[3])
        : "r"(a0), "r"(a1), "r"(a2), "r"(a3), "r"(b0), "r"(b1));
}

// ---------------------------------------------------------------------------
// K1 (persistent, fp16 m16n8k16, 3-split): pairwise logits.
// 296 CTAs (2/SM); each loops over <=4 (b, tile-pair) items.
// W splits built ONCE per CTA; b hi+lo fragments fused in one LDS.128.
// ---------------------------------------------------------------------------
__global__ __launch_bounds__(256, 2)
void k1_logits_tc(const float* __restrict__ x, const float* __restrict__ W,
                  const float* __restrict__ pb, const float* __restrict__ attw) {
    extern __shared__ float S[];
    uint4*  WP  = (uint4*)&S[OFF_WP];
    float4* XI4 = (float4*)&S[OFF_XIP];
    float4* XJ4 = (float4*)&S[OFF_XJP];

    int t = threadIdx.x, w = t >> 5, lane = t & 31;
    int g = lane >> 2, cc = lane & 3;

    // Build W splits (scaled by 16) once: one uint4 {hi01,hi89,lo01,lo89}
    for (int idx = t; idx < 1024; idx += 256) {
        int o = idx & 63, c2 = (idx >> 6) & 3, ks = idx >> 8;
        int d0 = 16 * ks + 2 * c2;
        float w0 = 16.0f * W[(d0    ) * DD + o];
        float w1 = 16.0f * W[(d0 + 1) * DD + o];
        float w8 = 16.0f * W[(d0 + 8) * DD + o];
        float w9 = 16.0f * W[(d0 + 9) * DD + o];
        __half2 h01 = __floats2half2_rn(w0, w1);
        __half2 h89 = __floats2half2_rn(w8, w9);
        float2 f01 = __half22float2(h01);
        float2 f89 = __half22float2(h89);
        __half2 l01 = __floats2half2_rn(w0 - f01.x, w1 - f01.y);
        __half2 l89 = __floats2half2_rn(w8 - f89.x, w9 - f89.y);
        WP[(ks * 64 + o) * 4 + c2] = make_uint4(h2u(h01), h2u(h89), h2u(l01), h2u(l89));
    }
    if (t < DD) { S[OFF_PB + t] = pb[t]; S[OFF_AW + t] = attw[t]; }

    #pragma unroll 1
    for (int item = blockIdx.x; item < NITEMS; item += K1GRID) {
        int b = item >> 7;                 // item / 136... careful: 136 not pow2
        b = item / NPAIRS;
        int pp = item - b * NPAIRS;
        int it = 0;
        while (pp >= NTILES - it) { pp -= NTILES - it; it++; }
        int jt = it + pp;

        const float* xb = x + (size_t)b * NN * DD;
        for (int idx = t; idx < 512; idx += 256) {
            int ks = idx >> 7, r = (idx >> 2) & 31, c2 = idx & 3;
            int d0 = 16 * ks + 2 * c2;
            const float* xi = xb + (it * TILE + r) * DD;
            const float* xj = xb + (jt * TILE + r) * DD;
            XI4[idx] = make_float4(xi[d0], xi[d0 + 1], xi[d0 + 8], xi[d0 + 9]);
            XJ4[idx] = make_float4(xj[d0], xj[d0 + 1], xj[d0 + 8], xj[d0 + 9]);
        }
        __syncthreads();

        float* L = g_logits + (size_t)b * NN * NN;

        #pragma unroll 1
        for (int p = 0; p < 4; p++) {
            int iL = 4 * w + p;                 // this warp's i row (local)
            float C[2][8][4];                   // [j-half][o-tile][frag]
            #pragma unroll
            for (int h = 0; h < 2; h++)
                #pragma unroll
                for (int nt = 0; nt < 8; nt++)
                    #pragma unroll
                    for (int q = 0; q < 4; q++) C[h][nt][q] = 0.f;

            #pragma unroll 1
            for (int ks = 0; ks < 4; ks++) {
                float4 ai = XI4[(ks * TILE + iL) * 4 + cc];
                unsigned ah[2][4], al[2][4];
                #pragma unroll
                for (int h = 0; h < 2; h++) {
                    int jb = h * 16;
                    float4 ajg = XJ4[(ks * TILE + jb + g    ) * 4 + cc];
                    float4 aj8 = XJ4[(ks * TILE + jb + g + 8) * 4 + cc];
                    float pg0 = ai.x * ajg.x, pg1 = ai.y * ajg.y;
                    float pg8 = ai.z * ajg.z, pg9 = ai.w * ajg.w;
                    float q0  = ai.x * aj8.x, q1  = ai.y * aj8.y;
                    float q8  = ai.z * aj8.z, q9  = ai.w * aj8.w;
                    __half2 h0 = __floats2half2_rn(pg0, pg1);   // a0: row g, k lo
                    __half2 h1 = __floats2half2_rn(q0, q1);     // a1: row g+8, k lo
                    __half2 h2 = __floats2half2_rn(pg8, pg9);   // a2: row g, k hi
                    __half2 h3 = __floats2half2_rn(q8, q9);     // a3: row g+8, k hi
                    float2 f0 = __half22float2(h0), f1 = __half22float2(h1);
                    float2 f2 = __half22float2(h2), f3 = __half22float2(h3);
                    ah[h][0] = h2u(h0); ah[h][1] = h2u(h1);
                    ah[h][2] = h2u(h2); ah[h][3] = h2u(h3);
                    al[h][0] = h2u(__floats2half2_rn(pg0 - f0.x, pg1 - f0.y));
                    al[h][1] = h2u(__floats2half2_rn(q0  - f1.x, q1  - f1.y));
                    al[h][2] = h2u(__floats2half2_rn(pg8 - f2.x, pg9 - f2.y));
                    al[h][3] = h2u(__floats2half2_rn(q8  - f3.x, q9  - f3.y));
                }
                // one LDS.128 per nt = b hi AND lo fragments; 6 MMAs each
                #pragma unroll
                for (int nt = 0; nt < 8; nt++) {
                    uint4 bp = WP[(ks * DD + nt * 8 + g) * 4 + cc];
                    mma_f16(C[0][nt], ah[0][0], ah[0][1], ah[0][2], ah[0][3], bp.x, bp.y);
                    mma_f16(C[1][nt], ah[1][0], ah[1][1], ah[1][2], ah[1][3], bp.x, bp.y);
                    mma_f16(C[0][nt], al[0][0], al[0][1], al[0][2], al[0][3], bp.x, bp.y);
                    mma_f16(C[1][nt], al[1][0], al[1][1], al[1][2], al[1][3], bp.x, bp.y);
                    mma_f16(C[0][nt], ah[0][0], ah[0][1], ah[0][2], ah[0][3], bp.z, bp.w);
                    mma_f16(C[1][nt], ah[1][0], ah[1][1], ah[1][2], ah[1][3], bp.z, bp.w);
                }
            }
            // epilogue: tanh(C/16 + pb) . attw, quad-shuffle o-reduce, store+mirror
            int gi = it * TILE + iL;
            #pragma unroll
            for (int h = 0; h < 2; h++) {
                float slo = 0.f, shi = 0.f;
                #pragma unroll
                for (int nt = 0; nt < 8; nt++) {
                    int o0 = nt * 8 + 2 * cc, o1 = o0 + 1;
                    float pb0 = S[OFF_PB + o0], pb1 = S[OFF_PB + o1];
                    float w0  = S[OFF_AW + o0], w1  = S[OFF_AW + o1];
                    slo = fmaf(fast_tanh(fmaf(C[h][nt][0], 0.0625f, pb0)), w0, slo);
                    slo = fmaf(fast_tanh(fmaf(C[h][nt][1], 0.0625f, pb1)), w1, slo);
                    shi = fmaf(fast_tanh(fmaf(C[h][nt][2], 0.0625f, pb0)), w0, shi);
                    shi = fmaf(fast_tanh(fmaf(C[h][nt][3], 0.0625f, pb1)), w1, shi);
                }
                slo += __shfl_xor_sync(0xffffffffu, slo, 1);
                slo += __shfl_xor_sync(0xffffffffu, slo, 2);
                shi += __shfl_xor_sync(0xffffffffu, shi, 1);
                shi += __shfl_xor_sync(0xffffffffu, shi, 2);
                if (cc == 0) {
                    int gj0 = jt * TILE + h * 16 + g;
                    int gj8 = gj0 + 8;
                    L[gi * NN + gj0] = slo;
                    L[gi * NN + gj8] = shi;
                    if (it != jt) {
                        L[gj0 * NN + gi] = slo;
                        L[gj8 * NN + gi] = shi;
                    }
                }
            }
        }
        __syncthreads();   // readers done before next item's XI/XJ overwrite
    }
}

// ---------------------------------------------------------------------------
// K2: per (b, 8-row block): softmax over j, agg = att @ X, h = agg@pwa + x@pwo
//     + biases, BN(eval), SELU, score = sigmoid(h @ pool_w + pool_b)
// ---------------------------------------------------------------------------
__global__ __launch_bounds__(256)
void k2_softagg(const float* __restrict__ x,
                const float* __restrict__ pwa_w, const float* __restrict__ pwa_b,
                const float* __restrict__ pwo_w, const float* __restrict__ pwo_b,
                const float* __restrict__ bn_gamma, const float* __restrict__ bn_beta,
                const float* __restrict__ pool_w, const float* __restrict__ pool_b) {
    __shared__ float prob_s[NN][8];        // 16 KB: [j][r]
    __shared__ float part_s[4][8][DD];     // 8 KB
    __shared__ float agg_s[8][DD];
    __shared__ float xrow_s[8][DD];
    __shared__ float h_s[8][DD];
    __shared__ float inv_s[8];

    int b = blockIdx.y;
    int ibase = blockIdx.x * 8;
    int t = threadIdx.x;
    const float* xb = x + (size_t)b * NN * DD;

    for (int idx = t; idx < 8 * DD; idx += 256) {
        int r = idx >> 6, d = idx & 63;
        xrow_s[r][d] = xb[(ibase + r) * DD + d];
    }

    {   // softmax (unnormalized) for 8 rows: warp r handles row ibase+r
        int r = t >> 5, lane = t & 31;
        const float* Lrow = g_logits + ((size_t)b * NN + ibase + r) * NN;
        float lv[16];
        float m = -1e30f;
        #pragma unroll
        for (int q = 0; q < 16; q++) { lv[q] = Lrow[lane + q * 32]; m = fmaxf(m, lv[q]); }
        #pragma unroll
        for (int off = 16; off; off >>= 1) m = fmaxf(m, __shfl_xor_sync(0xffffffffu, m, off));
        float sum = 0.f;
        #pragma unroll
        for (int q = 0; q < 16; q++) {
            float e = __expf(lv[q] - m);
            prob_s[lane + q * 32][r] = e;
            sum += e;
        }
        #pragma unroll
        for (int off = 16; off; off >>= 1) sum += __shfl_xor_sync(0xffffffffu, sum, off);
        if (lane == 0) inv_s[r] = 1.0f / sum;
    }
    __syncthreads();

    {   // agg partials: thread = (d4 in 16, g in 4, rp in 4) -> 4 d x 2 rows
        int d4 = t & 15, g = (t >> 4) & 3, rp = t >> 6;
        int r0 = rp * 2;
        float a0x=0,a0y=0,a0z=0,a0w=0, a1x=0,a1y=0,a1z=0,a1w=0;
        const float4* xb4 = (const float4*)xb;
        for (int jj = 0; jj < 128; jj++) {
            int j = g * 128 + jj;
            float4 xv = xb4[j * 16 + d4];
            float2 pr = *(const float2*)&prob_s[j][r0];
            a0x = fmaf(pr.x, xv.x, a0x); a0y = fmaf(pr.x, xv.y, a0y);
            a0z = fmaf(pr.x, xv.z, a0z); a0w = fmaf(pr.x, xv.w, a0w);
            a1x = fmaf(pr.y, xv.x, a1x); a1y = fmaf(pr.y, xv.y, a1y);
            a1z = fmaf(pr.y, xv.z, a1z); a1w = fmaf(pr.y, xv.w, a1w);
        }
        part_s[g][r0][d4*4+0] = a0x; part_s[g][r0][d4*4+1] = a0y;
        part_s[g][r0][d4*4+2] = a0z; part_s[g][r0][d4*4+3] = a0w;
        part_s[g][r0+1][d4*4+0] = a1x; part_s[g][r0+1][d4*4+1] = a1y;
        part_s[g][r0+1][d4*4+2] = a1z; part_s[g][r0+1][d4*4+3] = a1w;
    }
    __syncthreads();

    if (t < DD) {
        int d = t;
        #pragma unroll
        for (int r = 0; r < 8; r++) {
            float s = part_s[0][r][d] + part_s[1][r][d] + part_s[2][r][d] + part_s[3][r][d];
            agg_s[r][d] = s * inv_s[r];
        }
    }
    __syncthreads();

    {   // projections + BN + SELU: thread = (o in 64, rr in 4) -> 2 rows
        int o = t & 63, rr = t >> 6;
        int r0 = rr * 2, r1 = r0 + 1;
        float acc0 = pwa_b[o] + pwo_b[o];
        float acc1 = acc0;
        #pragma unroll 8
        for (int d = 0; d < DD; d++) {
            float wa = pwa_w[d * DD + o];
            float wo = pwo_w[d * DD + o];
            acc0 = fmaf(agg_s[r0][d], wa, acc0);
            acc0 = fmaf(xrow_s[r0][d], wo, acc0);
            acc1 = fmaf(agg_s[r1][d], wa, acc1);
            acc1 = fmaf(xrow_s[r1][d], wo, acc1);
        }
        const float BNF = 0.9999950000374997f;   // 1/sqrt(1+1e-5)
        float gm = bn_gamma[o] * BNF, bt = bn_beta[o];
        acc0 = acc0 * gm + bt;
        acc1 = acc1 * gm + bt;
        const float SC = 1.0507009873554805f, AL = 1.6732632423543772f;
        float v0 = acc0 > 0.f ? SC * acc0 : SC * AL * expm1f(acc0);
        float v1 = acc1 > 0.f ? SC * acc1 : SC * AL * expm1f(acc1);
        g_h[((size_t)b * NN + ibase + r0) * DD + o] = v0;
        g_h[((size_t)b * NN + ibase + r1) * DD + o] = v1;
        h_s[r0][o] = v0; h_s[r1][o] = v1;
    }
    __syncthreads();

    {   // pool scores
        int r = t >> 5, lane = t & 31;
        float z = h_s[r][lane] * pool_w[lane] + h_s[r][lane + 32] * pool_w[lane + 32];
        #pragma unroll
        for (int off = 16; off; off >>= 1) z += __shfl_xor_sync(0xffffffffu, z, off);
        if (lane == 0) {
            z += pool_b[0];
            g_scores[b * NN + ibase + r] = __fdividef(1.0f, 1.0f + __expf(-z));
        }
    }
}

// ---------------------------------------------------------------------------
// K3: per batch: full bitonic sort of 512 (score desc, idx asc) keys,
//     emit top-256 rows of h*score in rank order.
// ---------------------------------------------------------------------------
__global__ __launch_bounds__(512)
void k3_topk(float* __restrict__ out) {
    __shared__ unsigned long long keys[NN];
    __shared__ int   s_idx[KNODES];
    __shared__ float s_sc[KNODES];
    int b = blockIdx.x, t = threadIdx.x;
    float s = g_scores[b * NN + t];
    // scores in (0,1): positive-float bit pattern is order-preserving.
    keys[t] = ((unsigned long long)__float_as_uint(s) << 16) | (unsigned)(0xFFFF - t);
    __syncthreads();
    for (int k = 2; k <= NN; k <<= 1) {
        for (int j = k >> 1; j > 0; j >>= 1) {
            int ixj = t ^ j;
            if (ixj > t) {
                unsigned long long a = keys[t], c = keys[ixj];
                bool sw = ((t & k) == 0) ? (a < c) : (a > c);   // descending
                if (sw) { keys[t] = c; keys[ixj] = a; }
            }
            __syncthreads();
        }
    }
    if (t < KNODES) {
        unsigned long long kk = keys[t];
        s_idx[t] = 0xFFFF - (int)(kk & 0xFFFF);
        s_sc[t] = __uint_as_float((unsigned)(kk >> 16));
    }
    __syncthreads();
    const float* hb = g_h + (size_t)b * NN * DD;
    float* ob = out + (size_t)b * KNODES * DD;
    for (int e = t; e < KNODES * DD; e += 512) {
        int r = e >> 6, o = e & 63;
        ob[e] = hb[s_idx[r] * DD + o] * s_sc[r];
    }
}

extern "C" void kernel_launch(void* const* d_in, const int* in_sizes, int n_in,
                              void* d_out, int out_size) {
    const float* x     = (const float*)d_in[0];
    const float* apw   = (const float*)d_in[1];
    const float* apb   = (const float*)d_in[2];
    const float* attw  = (const float*)d_in[3];
    const float* pwa_w = (const float*)d_in[4];
    const float* pwa_b = (const float*)d_in[5];
    const float* pwo_w = (const float*)d_in[6];
    const float* pwo_b = (const float*)d_in[7];
    const float* bng   = (const float*)d_in[8];
    const float* bnb   = (const float*)d_in[9];
    const float* plw   = (const float*)d_in[10];
    const float* plb   = (const float*)d_in[11];
    float* out = (float*)d_out;

    cudaFuncSetAttribute(k1_logits_tc, cudaFuncAttributeMaxDynamicSharedMemorySize, SMEM_BYTES);
    k1_logits_tc<<<K1GRID, 256, SMEM_BYTES>>>(x, apw, apb, attw);
    k2_softagg<<<dim3(NN / 8, BATCH), 256>>>(x, pwa_w, pwa_b, pwo_w, pwo_b,
                                             bng, bnb, plw, plb);
    k3_topk<<<BATCH, 512>>>(out);
}

// round 10
// speedup vs baseline: 1.5426x; 1.0124x over previous
#include <cuda_runtime.h>
#include <cuda_fp16.h>
#include <cstdint>

#define BATCH   8
#define NN      512
#define DD      64
#define KNODES  256
#define TILE    32
#define NTILES  16      // NN / TILE
#define NPAIRS  136     // NTILES*(NTILES+1)/2
#define NITEMS  (BATCH * NPAIRS)   // 1088
#define K1GRID  296                // 2 CTAs/SM * 148 SMs

// Scratch (device globals: no allocation allowed)
__device__ float g_logits[BATCH * NN * NN];   // 8 MB
__device__ float g_h[BATCH * NN * DD];        // 1 MB
__device__ float g_scores[BATCH * NN];

// k1 smem layout (float offsets)
//  WP:  uint4[4][64][4]: .xy = {h2(ws[16k+2c],ws[+1]), h2(ws[+8],ws[+9])} hi
//                        .zw = same, lo split   (ws = 16*W)
//  XIP/XJP: float4[4][32][4]: {x[r][16k+2c], [+1], [+8], [+9]}
#define OFF_WP  0
#define OFF_XIP 4096
#define OFF_XJP 6144
#define OFF_PB  8192
#define OFF_AW  8256
#define SMEM_FLOATS 8320
#define SMEM_BYTES  (SMEM_FLOATS * 4)

__device__ __forceinline__ float fast_tanh(float v) {
    // 1 - 2/(e^{2v}+1): correct saturation both directions, no abs/copysign
    float e = __expf(2.0f * v);
    return 1.0f - __fdividef(2.0f, e + 1.0f);
}

__device__ __forceinline__ unsigned h2u(__half2 h) {
    return *reinterpret_cast<unsigned*>(&h);
}

__device__ __forceinline__ void mma_f16(float* c,
                                        unsigned a0, unsigned a1, unsigned a2, unsigned a3,
                                        unsigned b0, unsigned b1) {
    asm("mma.sync.aligned.m16n8k16.row.col.f32.f16.f16.f32 "
        "{%0,%1,%2,%3}, {%4,%5,%6,%7}, {%8,%9}, {%0,%1,%2,%3};"
        : "+f"(c[0]), "+f"(c[1]), "+f"(c[2]), "+f"(c[3])
        : "r"(a0), "r"(a1), "r"(a2), "r"(a3), "r"(b0), "r"(b1));
}

// ---------------------------------------------------------------------------
// K1 (persistent, fp16 m16n8k16, 3-split): pairwise logits.
// 296 CTAs (2/SM); each loops over <=4 (b, tile-pair) items.
// b fragments register-cached in 4-nt groups; MMAs issued in 3 passes of 8
// independent ops (same-C RAW distance 8 >> HMMA latency). Per-accumulator
// accumulation order unchanged (hh, lh, hl per ks) -> bitwise-identical.
// ---------------------------------------------------------------------------
__global__ __launch_bounds__(256, 2)
void k1_logits_tc(const float* __restrict__ x, const float* __restrict__ W,
                  const float* __restrict__ pb, const float* __restrict__ attw) {
    extern __shared__ float S[];
    uint4*  WP  = (uint4*)&S[OFF_WP];
    float4* XI4 = (float4*)&S[OFF_XIP];
    float4* XJ4 = (float4*)&S[OFF_XJP];

    int t = threadIdx.x, w = t >> 5, lane = t & 31;
    int g = lane >> 2, cc = lane & 3;

    // Build W splits (scaled by 16) once: one uint4 {hi01,hi89,lo01,lo89}
    for (int idx = t; idx < 1024; idx += 256) {
        int o = idx & 63, c2 = (idx >> 6) & 3, ks = idx >> 8;
        int d0 = 16 * ks + 2 * c2;
        float w0 = 16.0f * W[(d0    ) * DD + o];
        float w1 = 16.0f * W[(d0 + 1) * DD + o];
        float w8 = 16.0f * W[(d0 + 8) * DD + o];
        float w9 = 16.0f * W[(d0 + 9) * DD + o];
        __half2 h01 = __floats2half2_rn(w0, w1);
        __half2 h89 = __floats2half2_rn(w8, w9);
        float2 f01 = __half22float2(h01);
        float2 f89 = __half22float2(h89);
        __half2 l01 = __floats2half2_rn(w0 - f01.x, w1 - f01.y);
        __half2 l89 = __floats2half2_rn(w8 - f89.x, w9 - f89.y);
        WP[(ks * 64 + o) * 4 + c2] = make_uint4(h2u(h01), h2u(h89), h2u(l01), h2u(l89));
    }
    if (t < DD) { S[OFF_PB + t] = pb[t]; S[OFF_AW + t] = attw[t]; }

    #pragma unroll 1
    for (int item = blockIdx.x; item < NITEMS; item += K1GRID) {
        int b = item / NPAIRS;
        int pp = item - b * NPAIRS;
        int it = 0;
        while (pp >= NTILES - it) { pp -= NTILES - it; it++; }
        int jt = it + pp;

        const float* xb = x + (size_t)b * NN * DD;
        for (int idx = t; idx < 512; idx += 256) {
            int ks = idx >> 7, r = (idx >> 2) & 31, c2 = idx & 3;
            int d0 = 16 * ks + 2 * c2;
            const float* xi = xb + (it * TILE + r) * DD;
            const float* xj = xb + (jt * TILE + r) * DD;
            XI4[idx] = make_float4(xi[d0], xi[d0 + 1], xi[d0 + 8], xi[d0 + 9]);
            XJ4[idx] = make_float4(xj[d0], xj[d0 + 1], xj[d0 + 8], xj[d0 + 9]);
        }
        __syncthreads();

        float* L = g_logits + (size_t)b * NN * NN;

        #pragma unroll 1
        for (int p = 0; p < 4; p++) {
            int iL = 4 * w + p;                 // this warp's i row (local)
            float C[2][8][4];                   // [j-half][o-tile][frag]
            #pragma unroll
            for (int h = 0; h < 2; h++)
                #pragma unroll
                for (int nt = 0; nt < 8; nt++)
                    #pragma unroll
                    for (int q = 0; q < 4; q++) C[h][nt][q] = 0.f;

            #pragma unroll 1
            for (int ks = 0; ks < 4; ks++) {
                float4 ai = XI4[(ks * TILE + iL) * 4 + cc];
                unsigned ah[2][4], al[2][4];
                #pragma unroll
                for (int h = 0; h < 2; h++) {
                    int jb = h * 16;
                    float4 ajg = XJ4[(ks * TILE + jb + g    ) * 4 + cc];
                    float4 aj8 = XJ4[(ks * TILE + jb + g + 8) * 4 + cc];
                    float pg0 = ai.x * ajg.x, pg1 = ai.y * ajg.y;
                    float pg8 = ai.z * ajg.z, pg9 = ai.w * ajg.w;
                    float q0  = ai.x * aj8.x, q1  = ai.y * aj8.y;
                    float q8  = ai.z * aj8.z, q9  = ai.w * aj8.w;
                    __half2 h0 = __floats2half2_rn(pg0, pg1);   // a0: row g, k lo
                    __half2 h1 = __floats2half2_rn(q0, q1);     // a1: row g+8, k lo
                    __half2 h2 = __floats2half2_rn(pg8, pg9);   // a2: row g, k hi
                    __half2 h3 = __floats2half2_rn(q8, q9);     // a3: row g+8, k hi
                    float2 f0 = __half22float2(h0), f1 = __half22float2(h1);
                    float2 f2 = __half22float2(h2), f3 = __half22float2(h3);
                    ah[h][0] = h2u(h0); ah[h][1] = h2u(h1);
                    ah[h][2] = h2u(h2); ah[h][3] = h2u(h3);
                    al[h][0] = h2u(__floats2half2_rn(pg0 - f0.x, pg1 - f0.y));
                    al[h][1] = h2u(__floats2half2_rn(q0  - f1.x, q1  - f1.y));
                    al[h][2] = h2u(__floats2half2_rn(pg8 - f2.x, pg9 - f2.y));
                    al[h][3] = h2u(__floats2half2_rn(q8  - f3.x, q9  - f3.y));
                }
                // 4-nt groups: preload b into regs, 3 passes of 8 independent
                // MMAs; same-C RAW distance = 8 (>> HMMA latency).
                #pragma unroll
                for (int ng = 0; ng < 2; ng++) {
                    uint4 bp[4];
                    #pragma unroll
                    for (int q = 0; q < 4; q++)
                        bp[q] = WP[(ks * DD + (ng * 4 + q) * 8 + g) * 4 + cc];
                    // pass 1: a_hi * b_hi
                    #pragma unroll
                    for (int q = 0; q < 4; q++) {
                        int nt = ng * 4 + q;
                        mma_f16(C[0][nt], ah[0][0], ah[0][1], ah[0][2], ah[0][3], bp[q].x, bp[q].y);
                        mma_f16(C[1][nt], ah[1][0], ah[1][1], ah[1][2], ah[1][3], bp[q].x, bp[q].y);
                    }
                    // pass 2: a_lo * b_hi
                    #pragma unroll
                    for (int q = 0; q < 4; q++) {
                        int nt = ng * 4 + q;
                        mma_f16(C[0][nt], al[0][0], al[0][1], al[0][2], al[0][3], bp[q].x, bp[q].y);
                        mma_f16(C[1][nt], al[1][0], al[1][1], al[1][2], al[1][3], bp[q].x, bp[q].y);
                    }
                    // pass 3: a_hi * b_lo
                    #pragma unroll
                    for (int q = 0; q < 4; q++) {
                        int nt = ng * 4 + q;
                        mma_f16(C[0][nt], ah[0][0], ah[0][1], ah[0][2], ah[0][3], bp[q].z, bp[q].w);
                        mma_f16(C[1][nt], ah[1][0], ah[1][1], ah[1][2], ah[1][3], bp[q].z, bp[q].w);
                    }
                }
            }
            // epilogue: tanh(C/16 + pb) . attw, quad-shuffle o-reduce, store+mirror
            int gi = it * TILE + iL;
            #pragma unroll
            for (int h = 0; h < 2; h++) {
                float slo = 0.f, shi = 0.f;
                #pragma unroll
                for (int nt = 0; nt < 8; nt++) {
                    int o0 = nt * 8 + 2 * cc, o1 = o0 + 1;
                    float pb0 = S[OFF_PB + o0], pb1 = S[OFF_PB + o1];
                    float w0  = S[OFF_AW + o0], w1  = S[OFF_AW + o1];
                    slo = fmaf(fast_tanh(fmaf(C[h][nt][0], 0.0625f, pb0)), w0, slo);
                    slo = fmaf(fast_tanh(fmaf(C[h][nt][1], 0.0625f, pb1)), w1, slo);
                    shi = fmaf(fast_tanh(fmaf(C[h][nt][2], 0.0625f, pb0)), w0, shi);
                    shi = fmaf(fast_tanh(fmaf(C[h][nt][3], 0.0625f, pb1)), w1, shi);
                }
                slo += __shfl_xor_sync(0xffffffffu, slo, 1);
                slo += __shfl_xor_sync(0xffffffffu, slo, 2);
                shi += __shfl_xor_sync(0xffffffffu, shi, 1);
                shi += __shfl_xor_sync(0xffffffffu, shi, 2);
                if (cc == 0) {
                    int gj0 = jt * TILE + h * 16 + g;
                    int gj8 = gj0 + 8;
                    L[gi * NN + gj0] = slo;
                    L[gi * NN + gj8] = shi;
                    if (it != jt) {
                        L[gj0 * NN + gi] = slo;
                        L[gj8 * NN + gi] = shi;
                    }
                }
            }
        }
        __syncthreads();   // readers done before next item's XI/XJ overwrite
    }
}

// ---------------------------------------------------------------------------
// K2: per (b, 8-row block): softmax over j, agg = att @ X, h = agg@pwa + x@pwo
//     + biases, BN(eval), SELU, score = sigmoid(h @ pool_w + pool_b)
// prob_s stride 10: softmax STS 8-way conflict -> 2-way; float2 reads aligned.
// ---------------------------------------------------------------------------
#define PRS 10
__global__ __launch_bounds__(256)
void k2_softagg(const float* __restrict__ x,
                const float* __restrict__ pwa_w, const float* __restrict__ pwa_b,
                const float* __restrict__ pwo_w, const float* __restrict__ pwo_b,
                const float* __restrict__ bn_gamma, const float* __restrict__ bn_beta,
                const float* __restrict__ pool_w, const float* __restrict__ pool_b) {
    __shared__ float prob_s[NN][PRS];      // 20 KB: [j][r] (stride 10)
    __shared__ float part_s[4][8][DD];     // 8 KB
    __shared__ float agg_s[8][DD];
    __shared__ float xrow_s[8][DD];
    __shared__ float h_s[8][DD];
    __shared__ float inv_s[8];

    int b = blockIdx.y;
    int ibase = blockIdx.x * 8;
    int t = threadIdx.x;
    const float* xb = x + (size_t)b * NN * DD;

    for (int idx = t; idx < 8 * DD; idx += 256) {
        int r = idx >> 6, d = idx & 63;
        xrow_s[r][d] = xb[(ibase + r) * DD + d];
    }

    {   // softmax (unnormalized) for 8 rows: warp r handles row ibase+r
        int r = t >> 5, lane = t & 31;
        const float* Lrow = g_logits + ((size_t)b * NN + ibase + r) * NN;
        float lv[16];
        float m = -1e30f;
        #pragma unroll
        for (int q = 0; q < 16; q++) { lv[q] = Lrow[lane + q * 32]; m = fmaxf(m, lv[q]); }
        #pragma unroll
        for (int off = 16; off; off >>= 1) m = fmaxf(m, __shfl_xor_sync(0xffffffffu, m, off));
        float sum = 0.f;
        #pragma unroll
        for (int q = 0; q < 16; q++) {
            float e = __expf(lv[q] - m);
            prob_s[lane + q * 32][r] = e;
            sum += e;
        }
        #pragma unroll
        for (int off = 16; off; off >>= 1) sum += __shfl_xor_sync(0xffffffffu, sum, off);
        if (lane == 0) inv_s[r] = 1.0f / sum;
    }
    __syncthreads();

    {   // agg partials: thread = (d4 in 16, g in 4, rp in 4) -> 4 d x 2 rows
        int d4 = t & 15, g = (t >> 4) & 3, rp = t >> 6;
        int r0 = rp * 2;
        float a0x=0,a0y=0,a0z=0,a0w=0, a1x=0,a1y=0,a1z=0,a1w=0;
        const float4* xb4 = (const float4*)xb;
        for (int jj = 0; jj < 128; jj++) {
            int j = g * 128 + jj;
            float4 xv = xb4[j * 16 + d4];
            float2 pr = *(const float2*)&prob_s[j][r0];
            a0x = fmaf(pr.x, xv.x, a0x); a0y = fmaf(pr.x, xv.y, a0y);
            a0z = fmaf(pr.x, xv.z, a0z); a0w = fmaf(pr.x, xv.w, a0w);
            a1x = fmaf(pr.y, xv.x, a1x); a1y = fmaf(pr.y, xv.y, a1y);
            a1z = fmaf(pr.y, xv.z, a1z); a1w = fmaf(pr.y, xv.w, a1w);
        }
        part_s[g][r0][d4*4+0] = a0x; part_s[g][r0][d4*4+1] = a0y;
        part_s[g][r0][d4*4+2] = a0z; part_s[g][r0][d4*4+3] = a0w;
        part_s[g][r0+1][d4*4+0] = a1x; part_s[g][r0+1][d4*4+1] = a1y;
        part_s[g][r0+1][d4*4+2] = a1z; part_s[g][r0+1][d4*4+3] = a1w;
    }
    __syncthreads();

    if (t < DD) {
        int d = t;
        #pragma unroll
        for (int r = 0; r < 8; r++) {
            float s = part_s[0][r][d] + part_s[1][r][d] + part_s[2][r][d] + part_s[3][r][d];
            agg_s[r][d] = s * inv_s[r];
        }
    }
    __syncthreads();

    {   // projections + BN + SELU: thread = (o in 64, rr in 4) -> 2 rows
        int o = t & 63, rr = t >> 6;
        int r0 = rr * 2, r1 = r0 + 1;
        float acc0 = pwa_b[o] + pwo_b[o];
        float acc1 = acc0;
        #pragma unroll 8
        for (int d = 0; d < DD; d++) {
            float wa = pwa_w[d * DD + o];
            float wo = pwo_w[d * DD + o];
            acc0 = fmaf(agg_s[r0][d], wa, acc0);
            acc0 = fmaf(xrow_s[r0][d], wo, acc0);
            acc1 = fmaf(agg_s[r1][d], wa, acc1);
            acc1 = fmaf(xrow_s[r1][d], wo, acc1);
        }
        const float BNF = 0.9999950000374997f;   // 1/sqrt(1+1e-5)
        float gm = bn_gamma[o] * BNF, bt = bn_beta[o];
        acc0 = acc0 * gm + bt;
        acc1 = acc1 * gm + bt;
        const float SC = 1.0507009873554805f, AL = 1.6732632423543772f;
        float v0 = acc0 > 0.f ? SC * acc0 : SC * AL * expm1f(acc0);
        float v1 = acc1 > 0.f ? SC * acc1 : SC * AL * expm1f(acc1);
        g_h[((size_t)b * NN + ibase + r0) * DD + o] = v0;
        g_h[((size_t)b * NN + ibase + r1) * DD + o] = v1;
        h_s[r0][o] = v0; h_s[r1][o] = v1;
    }
    __syncthreads();

    {   // pool scores
        int r = t >> 5, lane = t & 31;
        float z = h_s[r][lane] * pool_w[lane] + h_s[r][lane + 32] * pool_w[lane + 32];
        #pragma unroll
        for (int off = 16; off; off >>= 1) z += __shfl_xor_sync(0xffffffffu, z, off);
        if (lane == 0) {
            z += pool_b[0];
            g_scores[b * NN + ibase + r] = __fdividef(1.0f, 1.0f + __expf(-z));
        }
    }
}

// ---------------------------------------------------------------------------
// K3: per batch: full bitonic sort of 512 (score desc, idx asc) keys,
//     emit top-256 rows of h*score in rank order.
// ---------------------------------------------------------------------------
__global__ __launch_bounds__(512)
void k3_topk(float* __restrict__ out) {
    __shared__ unsigned long long keys[NN];
    __shared__ int   s_idx[KNODES];
    __shared__ float s_sc[KNODES];
    int b = blockIdx.x, t = threadIdx.x;
    float s = g_scores[b * NN + t];
    // scores in (0,1): positive-float bit pattern is order-preserving.
    keys[t] = ((unsigned long long)__float_as_uint(s) << 16) | (unsigned)(0xFFFF - t);
    __syncthreads();
    for (int k = 2; k <= NN; k <<= 1) {
        for (int j = k >> 1; j > 0; j >>= 1) {
            int ixj = t ^ j;
            if (ixj > t) {
                unsigned long long a = keys[t], c = keys[ixj];
                bool sw = ((t & k) == 0) ? (a < c) : (a > c);   // descending
                if (sw) { keys[t] = c; keys[ixj] = a; }
            }
            __syncthreads();
        }
    }
    if (t < KNODES) {
        unsigned long long kk = keys[t];
        s_idx[t] = 0xFFFF - (int)(kk & 0xFFFF);
        s_sc[t] = __uint_as_float((unsigned)(kk >> 16));
    }
    __syncthreads();
    const float* hb = g_h + (size_t)b * NN * DD;
    float* ob = out + (size_t)b * KNODES * DD;
    for (int e = t; e < KNODES * DD; e += 512) {
        int r = e >> 6, o = e & 63;
        ob[e] = hb[s_idx[r] * DD + o] * s_sc[r];
    }
}

extern "C" void kernel_launch(void* const* d_in, const int* in_sizes, int n_in,
                              void* d_out, int out_size) {
    const float* x     = (const float*)d_in[0];
    const float* apw   = (const float*)d_in[1];
    const float* apb   = (const float*)d_in[2];
    const float* attw  = (const float*)d_in[3];
    const float* pwa_w = (const float*)d_in[4];
    const float* pwa_b = (const float*)d_in[5];
    const float* pwo_w = (const float*)d_in[6];
    const float* pwo_b = (const float*)d_in[7];
    const float* bng   = (const float*)d_in[8];
    const float* bnb   = (const float*)d_in[9];
    const float* plw   = (const float*)d_in[10];
    const float* plb   = (const float*)d_in[11];
    float* out = (float*)d_out;

    cudaFuncSetAttribute(k1_logits_tc, cudaFuncAttributeMaxDynamicSharedMemorySize, SMEM_BYTES);
    k1_logits_tc<<<K1GRID, 256, SMEM_BYTES>>>(x, apw, apb, attw);
    k2_softagg<<<dim3(NN / 8, BATCH), 256>>>(x, pwa_w, pwa_b, pwo_w, pwo_b,
                                             bng, bnb, plw, plb);
    k3_topk<<<BATCH, 512>>>(out);
}